// round 11
// baseline (speedup 1.0000x reference)
#include <cuda_runtime.h>
#include <cuda_fp16.h>
#include <mma.h>

using namespace nvcuda::wmma;

// ---------------------------------------------------------------------------
// LSTMActorCritic: NSEQ=256, T=1024, OBS=128, ACT=16, H=64, N=262144
//
//  K0 prep_kernel   : one-time fp32->fp16 weight conversion (MLP weights).
//  K1 mlp_gx_kernel : tensor-core fused GEMM chain per 128-row tile (R6-exact).
//  K2 lstm_kernel   : fp32 weight-stationary recurrence, 256 blocks x 2 seqs.
//                     NEW: the block's two independent chains run in ANTIPHASE
//                     (gate-dot of one seq overlaps the serial MUFU elementwise
//                     of the other), hiding the per-phase latency chains that
//                     barrier lockstep exposed. 2 barriers/step unchanged.
//  K3 heads_kernel  : R6-proven 128-thread version.
// ---------------------------------------------------------------------------

typedef unsigned long long ull;

#define NSEQ   256
#define TLEN   1024
#define NROWS  262144      // NSEQ*TLEN
#define OBSD   128
#define HID    64
#define GATES  256         // 4*HID
#define ACT    16
#define PF     8           // gx prefetch depth (steps), power of two

// Scratch
__device__ float d_gx [2ull * NROWS * GATES];   // 536 MB, gx = feat@Wih.T (no bias)
__device__ float d_lat[2ull * NROWS * HID];     // 134 MB

// Pre-converted fp16 weights (MLP path only)
__device__ __half g_w1h [2][64 * OBSD];
__device__ __half g_w2h [2][64 * 64];
__device__ __half g_wihh[2][GATES * HID];

// ---------------- packed fp32x2 helpers ----------------
__device__ __forceinline__ ull pk2(float lo, float hi) {
    ull r; asm("mov.b64 %0,{%1,%2};" : "=l"(r) : "f"(lo), "f"(hi)); return r;
}
__device__ __forceinline__ float hsum2(ull v) {
    float a, b; asm("mov.b64 {%0,%1}, %2;" : "=f"(a), "=f"(b) : "l"(v)); return a + b;
}
__device__ __forceinline__ void fma2(ull &acc, ull a, ull b) {
    asm("fma.rn.f32x2 %0,%1,%2,%0;" : "+l"(acc) : "l"(a), "l"(b));
}

__device__ __forceinline__ float sigmoidf_(float x) {
    return __fdividef(1.f, 1.f + __expf(-x));
}
__device__ __forceinline__ float tanhf_(float x) {
    float e = __expf(-2.f * fabsf(x));
    float t = __fdividef(1.f - e, 1.f + e);
    return copysignf(t, x);
}

// ---------------------------------------------------------------------------
// K0: weight prep
// ---------------------------------------------------------------------------
extern "C" __global__ void __launch_bounds__(256)
prep_kernel(const float* __restrict__ Wp1, const float* __restrict__ Wv1,
            const float* __restrict__ Wp2, const float* __restrict__ Wv2,
            const float* __restrict__ Wih_pi, const float* __restrict__ Wih_vf)
{
    const int tid = blockIdx.x * blockDim.x + threadIdx.x;
    const int nth = gridDim.x * blockDim.x;
    for (int i = tid; i < 64 * OBSD; i += nth) {
        g_w1h[0][i] = __float2half(Wp1[i]);
        g_w1h[1][i] = __float2half(Wv1[i]);
    }
    for (int i = tid; i < 64 * 64; i += nth) {
        g_w2h[0][i] = __float2half(Wp2[i]);
        g_w2h[1][i] = __float2half(Wv2[i]);
    }
    for (int i = tid; i < GATES * HID; i += nth) {
        g_wihh[0][i] = __float2half(Wih_pi[i]);
        g_wihh[1][i] = __float2half(Wih_vf[i]);
    }
}

// ---------------------------------------------------------------------------
// K1: tensor-core MLP + gate precompute (R6-exact). grid (2048,2), block 256.
// ---------------------------------------------------------------------------
extern "C" __global__ void __launch_bounds__(256)
mlp_gx_kernel(const float* __restrict__ obs,
              const float* __restrict__ bp1, const float* __restrict__ bp2,
              const float* __restrict__ bv1, const float* __restrict__ bv2)
{
    extern __shared__ char smem[];
    __half* s_x   = (__half*)(smem);             // ld 136 (region 36864B)
    float*  s_f   = (float*)(smem);              // ld 72  (alias)
    __half* s_w1  = (__half*)(smem + 36864);     // 16384B
    __half* s_w2  = (__half*)(smem + 53248);     // 8192B
    __half* s_wih = (__half*)(smem + 61440);     // 32768B
    __half* s_a   = (__half*)(smem + 94208);     // 18432B
    float*  s_b1  = (float*)(smem + 112640);
    float*  s_b2  = s_b1 + 64;

    const int tid    = threadIdx.x;
    const int warp   = tid >> 5;
    const int branch = blockIdx.y;

    const float* b1 = branch ? bv1 : bp1;
    const float* b2 = branch ? bv2 : bp2;
    float* gx = d_gx + (size_t)branch * NROWS * GATES;

    // stage fp16 weights (vectorized copies)
    {
        const uint4* w1g  = (const uint4*)g_w1h[branch];
        const uint4* w2g  = (const uint4*)g_w2h[branch];
        const uint4* wihg = (const uint4*)g_wihh[branch];
        uint4* w1s  = (uint4*)s_w1;
        uint4* w2s  = (uint4*)s_w2;
        uint4* wihs = (uint4*)s_wih;
        #pragma unroll
        for (int i = 0; i < 4; i++)  w1s[tid + 256 * i]  = w1g[tid + 256 * i];
        #pragma unroll
        for (int i = 0; i < 2; i++)  if (tid + 256 * i < 512) w2s[tid + 256 * i] = w2g[tid + 256 * i];
        #pragma unroll
        for (int i = 0; i < 8; i++)  wihs[tid + 256 * i] = wihg[tid + 256 * i];
    }
    if (tid < 64)       s_b1[tid]      = b1[tid];
    else if (tid < 128) s_b2[tid - 64] = b2[tid - 64];

    // stage obs tile fp16
    const size_t row0 = (size_t)blockIdx.x * 128;
    for (int i = tid; i < 128 * 128; i += 256) {
        int r = i >> 7, k = i & 127;
        s_x[r * 136 + k] = __float2half(obs[(row0 + r) * OBSD + k]);
    }
    __syncthreads();

    fragment<matrix_a, 16, 16, 16, __half, row_major> fa;
    fragment<matrix_b, 16, 16, 16, __half, col_major> fb;
    fragment<accumulator, 16, 16, 16, float> fc[4];

    // ---- Layer 1: [128x128] @ [128x64] ----
    #pragma unroll
    for (int n = 0; n < 4; n++) fill_fragment(fc[n], 0.0f);
    #pragma unroll
    for (int k = 0; k < 8; k++) {
        load_matrix_sync(fa, s_x + warp * 16 * 136 + k * 16, 136);
        #pragma unroll
        for (int n = 0; n < 4; n++) {
            load_matrix_sync(fb, s_w1 + n * 16 * 128 + k * 16, 128);
            mma_sync(fc[n], fa, fb, fc[n]);
        }
    }
    __syncthreads();
    #pragma unroll
    for (int n = 0; n < 4; n++)
        store_matrix_sync(s_f + warp * 16 * 72 + n * 16, fc[n], 72, mem_row_major);
    __syncthreads();
    for (int i = tid; i < 128 * 64; i += 256) {
        int r = i >> 6, c = i & 63;
        s_a[r * 72 + c] = __float2half(tanhf_(s_f[r * 72 + c] + s_b1[c]));
    }
    __syncthreads();

    // ---- Layer 2: [128x64] @ [64x64] ----
    #pragma unroll
    for (int n = 0; n < 4; n++) fill_fragment(fc[n], 0.0f);
    #pragma unroll
    for (int k = 0; k < 4; k++) {
        load_matrix_sync(fa, s_a + warp * 16 * 72 + k * 16, 72);
        #pragma unroll
        for (int n = 0; n < 4; n++) {
            load_matrix_sync(fb, s_w2 + n * 16 * 64 + k * 16, 64);
            mma_sync(fc[n], fa, fb, fc[n]);
        }
    }
    #pragma unroll
    for (int n = 0; n < 4; n++)
        store_matrix_sync(s_f + warp * 16 * 72 + n * 16, fc[n], 72, mem_row_major);
    __syncthreads();
    for (int i = tid; i < 128 * 64; i += 256) {
        int r = i >> 6, c = i & 63;
        s_a[r * 72 + c] = __float2half(tanhf_(s_f[r * 72 + c] + s_b2[c]));
    }
    __syncthreads();

    // ---- Gates: [128x64] @ [64x256], accumulators straight to gmem ----
    float* gxw = gx + (row0 + warp * 16) * GATES;
    #pragma unroll 1
    for (int ch = 0; ch < 4; ch++) {
        #pragma unroll
        for (int n = 0; n < 4; n++) fill_fragment(fc[n], 0.0f);
        #pragma unroll
        for (int k = 0; k < 4; k++) {
            load_matrix_sync(fa, s_a + warp * 16 * 72 + k * 16, 72);
            #pragma unroll
            for (int n = 0; n < 4; n++) {
                load_matrix_sync(fb, s_wih + (ch * 64 + n * 16) * 64 + k * 16, 64);
                mma_sync(fc[n], fa, fb, fc[n]);
            }
        }
        #pragma unroll
        for (int n = 0; n < 4; n++)
            store_matrix_sync(gxw + ch * 64 + n * 16, fc[n], GATES, mem_row_major);
    }
}

// ---------------------------------------------------------------------------
// K2: antiphase recurrent loop. 256 blocks x 256 threads, 2 seqs/block.
// Half-step 1: gates(B,t) overlapped with elementwise(A,t).
// Half-step 2: gates(A,t+1) overlapped with elementwise(B,t).
// ew lanes: 16 lanes in each of warps 0..3 (one per SMSP), j = warp*16+lane.
// Hazards: every gs/hs writer-reader pair separated by a barrier (2/step).
// ---------------------------------------------------------------------------
extern "C" __global__ void __launch_bounds__(256, 2)
lstm_kernel(const float* __restrict__ Whh_pi, const float* __restrict__ Whh_vf,
            const float* __restrict__ eps,
            const float* __restrict__ h0_pi, const float* __restrict__ c0_pi,
            const float* __restrict__ h0_vf, const float* __restrict__ c0_vf,
            const float* __restrict__ bih_pi, const float* __restrict__ bhh_pi,
            const float* __restrict__ bih_vf, const float* __restrict__ bhh_vf)
{
    const int tid  = threadIdx.x;
    const int lstm = blockIdx.x >> 7;
    const int sp   = blockIdx.x & 127;
    const int seqA = sp * 2;

    const float* Whh = lstm ? Whh_vf : Whh_pi;
    const float* h0  = lstm ? h0_vf  : h0_pi;
    const float* c0  = lstm ? c0_vf  : c0_pi;
    const float* bih = lstm ? bih_vf : bih_pi;
    const float* bhh = lstm ? bhh_vf : bhh_pi;
    const float* gx  = d_gx  + (size_t)lstm * NROWS * GATES;
    float*       lat = d_lat + (size_t)lstm * NROWS * HID;

    __shared__ __align__(16) float hs[2][HID];   // [seq][elem]
    __shared__ float gs[2][GATES];               // [seq][gate row]
    __shared__ float seps[2][TLEN];

    // stage episode-start rows for both sequences (coalesced)
    {
        const float4* eA = (const float4*)(eps + (size_t)seqA * TLEN);
        float4* sA = (float4*)seps[0];
        sA[tid]       = eA[tid];
        sA[tid + 256] = eA[tid + 256];
    }

    // Whh row tid -> 32 packed pairs in registers; bias folded
    ull wv[32];
    {
        const float4* wp = (const float4*)(Whh + tid * HID);
        #pragma unroll
        for (int i = 0; i < 16; i++) {
            float4 v = wp[i];
            wv[2*i]   = pk2(v.x, v.y);
            wv[2*i+1] = pk2(v.z, v.w);
        }
    }
    const float bg = bih[tid] + bhh[tid];

    // gx prefetch rings (PF steps ahead), one per sequence
    float gAb[PF], gBb[PF];
    const float* gxA = gx + (size_t)seqA * TLEN * GATES + tid;
    const float* gxB = gxA + (size_t)TLEN * GATES;
    #pragma unroll
    for (int p = 0; p < PF; p++) {
        gAb[p] = __ldg(gxA + (size_t)p * GATES);
        gBb[p] = __ldg(gxB + (size_t)p * GATES);
    }

    // elementwise identity: 16 lanes of warps 0..3 -> one ew warp per SMSP
    const int wrp = tid >> 5, lane = tid & 31;
    const bool ewt = (wrp < 4) && (lane < 16);
    const int j = wrp * 16 + lane;               // 0..63 when ewt

    float cA = 0.f, cB = 0.f;
    __syncthreads();                             // seps staged
    if (ewt) {
        float mA = 1.f - seps[0][0];
        float mB = 1.f - seps[1][0];
        hs[0][j] = h0[seqA * HID + j] * mA;
        cA       = c0[seqA * HID + j] * mA;
        hs[1][j] = h0[(seqA + 1) * HID + j] * mB;
        cB       = c0[(seqA + 1) * HID + j] * mB;
    }
    __syncthreads();

    // prologue: gates(A, 0)
    {
        const ulonglong2* h2 = (const ulonglong2*)hs[0];
        ull a0 = 0, a1 = 0, a2 = 0, a3 = 0;
        #pragma unroll
        for (int kk = 0; kk < 8; kk++) {
            ulonglong2 p = h2[2*kk], q = h2[2*kk+1];
            fma2(a0, wv[4*kk],   p.x); fma2(a1, wv[4*kk+1], p.y);
            fma2(a2, wv[4*kk+2], q.x); fma2(a3, wv[4*kk+3], q.y);
        }
        gs[0][tid] = gAb[0] + bg + hsum2(a0) + hsum2(a1) + hsum2(a2) + hsum2(a3);
        gAb[0] = __ldg(gxA + (size_t)PF * GATES);   // refill slot 0 with step PF
    }

    for (int tb = 0; tb < TLEN; tb += PF) {
        #pragma unroll
        for (int u = 0; u < PF; u++) {
            const int t = tb + u;
            __syncthreads();     // publishes gs[0](t) [+ hs[1](t-1) from prev half2]

            // ---- half 1: gates(B,t)  ||  elementwise(A,t) ----
            {
                const ulonglong2* h2 = (const ulonglong2*)hs[1];
                ull a0 = 0, a1 = 0, a2 = 0, a3 = 0;
                #pragma unroll
                for (int kk = 0; kk < 8; kk++) {
                    ulonglong2 p = h2[2*kk], q = h2[2*kk+1];
                    fma2(a0, wv[4*kk],   p.x); fma2(a1, wv[4*kk+1], p.y);
                    fma2(a2, wv[4*kk+2], q.x); fma2(a3, wv[4*kk+3], q.y);
                }
                gs[1][tid] = gBb[u] + bg + hsum2(a0) + hsum2(a1) + hsum2(a2) + hsum2(a3);
                if (t + PF < TLEN) gBb[u] = __ldg(gxB + (size_t)(t + PF) * GATES);

                if (ewt) {
                    float gi = gs[0][j],       gf = gs[0][64 + j];
                    float gg = gs[0][128 + j], go = gs[0][192 + j];
                    cA = sigmoidf_(gf) * cA + sigmoidf_(gi) * tanhf_(gg);
                    float h = sigmoidf_(go) * tanhf_(cA);
                    lat[((size_t)seqA * TLEN + t) * HID + j] = h;
                    float m = 1.f - seps[0][(t + 1) & (TLEN - 1)];
                    cA *= m;
                    hs[0][j] = h * m;
                }
            }
            __syncthreads();     // publishes gs[1](t) + hs[0](t)

            // ---- half 2: gates(A,t+1)  ||  elementwise(B,t) ----
            {
                if (t + 1 < TLEN) {
                    const int u1 = (u + 1) & (PF - 1);
                    const ulonglong2* h2 = (const ulonglong2*)hs[0];
                    ull a0 = 0, a1 = 0, a2 = 0, a3 = 0;
                    #pragma unroll
                    for (int kk = 0; kk < 8; kk++) {
                        ulonglong2 p = h2[2*kk], q = h2[2*kk+1];
                        fma2(a0, wv[4*kk],   p.x); fma2(a1, wv[4*kk+1], p.y);
                        fma2(a2, wv[4*kk+2], q.x); fma2(a3, wv[4*kk+3], q.y);
                    }
                    gs[0][tid] = gAb[u1] + bg + hsum2(a0) + hsum2(a1) + hsum2(a2) + hsum2(a3);
                    if (t + 1 + PF < TLEN) gAb[u1] = __ldg(gxA + (size_t)(t + 1 + PF) * GATES);
                }
                if (ewt) {
                    float gi = gs[1][j],       gf = gs[1][64 + j];
                    float gg = gs[1][128 + j], go = gs[1][192 + j];
                    cB = sigmoidf_(gf) * cB + sigmoidf_(gi) * tanhf_(gg);
                    float h = sigmoidf_(go) * tanhf_(cB);
                    lat[((size_t)(seqA + 1) * TLEN + t) * HID + j] = h;
                    float m = 1.f - seps[1][(t + 1) & (TLEN - 1)];
                    cB *= m;
                    hs[1][j] = h * m;
                }
            }
        }
    }
}

// ---------------------------------------------------------------------------
// K3: heads (R6-proven). grid 2048 blocks, 128 threads, 128 rows/block.
// ---------------------------------------------------------------------------
extern "C" __global__ void __launch_bounds__(128)
heads_kernel(const int* __restrict__ action,
             const float* __restrict__ Wa, const float* __restrict__ ba,
             const float* __restrict__ Wc, const float* __restrict__ bc,
             float* __restrict__ out)
{
    __shared__ float tile[64 * 129];
    __shared__ float was[ACT * HID];
    __shared__ float bas[ACT];
    __shared__ float wcs[HID];
    __shared__ float bcs;

    const int tid = threadIdx.x;
    const int r0  = blockIdx.x * 128;
    const float* lat_pi = d_lat;
    const float* lat_vf = d_lat + (size_t)NROWS * HID;

    for (int i = tid; i < ACT * HID; i += 128) was[i] = Wa[i];
    if (tid < ACT) bas[tid] = ba[tid];
    if (tid < HID) wcs[tid] = Wc[tid];
    if (tid == 0)  bcs = bc[0];

    for (int i = tid; i < 128 * HID; i += 128) {
        int r = i >> 6, k = i & 63;
        tile[k * 129 + r] = lat_pi[(size_t)r0 * HID + i];
    }
    __syncthreads();

    const int n = r0 + tid;
    float l[ACT];
    #pragma unroll
    for (int a = 0; a < ACT; a++) l[a] = bas[a];
    #pragma unroll 1
    for (int k = 0; k < HID; k++) {
        float x = tile[k * 129 + tid];
        #pragma unroll
        for (int a = 0; a < ACT; a++) l[a] = fmaf(was[a * HID + k], x, l[a]);
    }

    float m = l[0];
    #pragma unroll
    for (int a = 1; a < ACT; a++) m = fmaxf(m, l[a]);
    float se = 0.f;
    #pragma unroll
    for (int a = 0; a < ACT; a++) se += __expf(l[a] - m);
    float lse = m + __logf(se);
    float ent = 0.f;
    #pragma unroll
    for (int a = 0; a < ACT; a++) { float lp = l[a] - lse; ent += __expf(lp) * lp; }
    int   act   = action[n];
    float lpact = l[act] - lse;
    __syncthreads();

    for (int i = tid; i < 128 * HID; i += 128) {
        int r = i >> 6, k = i & 63;
        tile[k * 129 + r] = lat_vf[(size_t)r0 * HID + i];
    }
    __syncthreads();

    float v = bcs;
    #pragma unroll
    for (int k = 0; k < HID; k++) v = fmaf(wcs[k], tile[k * 129 + tid], v);

    out[n]             = lpact;
    out[NROWS + n]     = -ent;
    out[2 * NROWS + n] = v;
}

// ---------------------------------------------------------------------------
extern "C" void kernel_launch(void* const* d_in, const int* in_sizes, int n_in,
                              void* d_out, int out_size)
{
    const float* obs     = (const float*)d_in[0];
    const int*   action  = (const int*)  d_in[1];
    const float* eps     = (const float*)d_in[2];
    const float* h_pi    = (const float*)d_in[3];
    const float* c_pi    = (const float*)d_in[4];
    const float* h_vf    = (const float*)d_in[5];
    const float* c_vf    = (const float*)d_in[6];
    const float* Wp1     = (const float*)d_in[7];
    const float* bp1     = (const float*)d_in[8];
    const float* Wp2     = (const float*)d_in[9];
    const float* bp2     = (const float*)d_in[10];
    const float* Wv1     = (const float*)d_in[11];
    const float* bv1     = (const float*)d_in[12];
    const float* Wv2     = (const float*)d_in[13];
    const float* bv2     = (const float*)d_in[14];
    const float* Wih_pi  = (const float*)d_in[15];
    const float* Whh_pi  = (const float*)d_in[16];
    const float* bih_pi  = (const float*)d_in[17];
    const float* bhh_pi  = (const float*)d_in[18];
    const float* Wih_vf  = (const float*)d_in[19];
    const float* Whh_vf  = (const float*)d_in[20];
    const float* bih_vf  = (const float*)d_in[21];
    const float* bhh_vf  = (const float*)d_in[22];
    const float* Wa      = (const float*)d_in[23];
    const float* ba      = (const float*)d_in[24];
    const float* Wc      = (const float*)d_in[25];
    const float* bc      = (const float*)d_in[26];
    float* out = (float*)d_out;

    const int SMEM_MLP = 114688;
    cudaFuncSetAttribute(mlp_gx_kernel, cudaFuncAttributeMaxDynamicSharedMemorySize, SMEM_MLP);

    prep_kernel<<<64, 256>>>(Wp1, Wv1, Wp2, Wv2, Wih_pi, Wih_vf);

    mlp_gx_kernel<<<dim3(2048, 2), 256, SMEM_MLP>>>(obs, bp1, bp2, bv1, bv2);

    lstm_kernel<<<256, 256>>>(Whh_pi, Whh_vf, eps, h_pi, c_pi, h_vf, c_vf,
                              bih_pi, bhh_pi, bih_vf, bhh_vf);

    heads_kernel<<<2048, 128>>>(action, Wa, ba, Wc, bc, out);
}